// round 5
// baseline (speedup 1.0000x reference)
#include <cuda_runtime.h>
#include <math.h>

#define IN_F   4096
#define OUT_F  4096
#define NROWS  16384
#define RANK   409
#define KA     4608               // A row stride: [g*x (4096) | t (512)]
#define N_LR   512                // lowrank N padded (4 tiles of 128)
#define XB     683
#define NBLOCKS (683*683)
#define KSEL   46649

#define BM 128
#define BN 128
#define BKC 128                   // k per chunk (s8) = 128B rows
#define TILE_B 16384              // 128 rows x 128B
#define STG    (4*TILE_B)         // A1,A2,B1,B2 per stage = 64KB
#define NSTAGE 3
#define SMEM_GEMM (NSTAGE*STG)    // 196608

// ============================================================================
// helpers
// ============================================================================
__device__ __forceinline__ unsigned smem_u32(const void* p) {
    unsigned a;
    asm("{ .reg .u64 t; cvta.to.shared.u64 t, %1; cvt.u32.u64 %0, t; }" : "=r"(a) : "l"(p));
    return a;
}
__device__ __forceinline__ void cpasync16(unsigned dst, const void* src) {
    asm volatile("cp.async.cg.shared.global [%0], [%1], 16;" :: "r"(dst), "l"(src));
}
#define CP_COMMIT() asm volatile("cp.async.commit_group;" ::: "memory")
#define CP_WAIT1()  asm volatile("cp.async.wait_group 1;" ::: "memory")

__device__ __forceinline__ uint4 ldsm4(unsigned a) {
    uint4 r;
    asm volatile("ldmatrix.sync.aligned.m8n8.x4.shared.b16 {%0,%1,%2,%3}, [%4];"
                 : "=r"(r.x), "=r"(r.y), "=r"(r.z), "=r"(r.w) : "r"(a));
    return r;
}
// s8 int MMA: m16n8k32, s32 accumulate
__device__ __forceinline__ void imma(int* c, uint4 a, unsigned b0, unsigned b1) {
    asm volatile("mma.sync.aligned.m16n8k32.row.col.s32.s8.s8.s32 "
                 "{%0,%1,%2,%3},{%4,%5,%6,%7},{%8,%9},{%0,%1,%2,%3};"
                 : "+r"(c[0]), "+r"(c[1]), "+r"(c[2]), "+r"(c[3])
                 : "r"(a.x), "r"(a.y), "r"(a.z), "r"(a.w), "r"(b0), "r"(b1));
}
// 2-limb s8 quantization: v*scale -> l1 + l2/256
__device__ __forceinline__ void q2(float v, float s, int& l1, int& l2) {
    float t = v * s;
    float f1 = rintf(t);
    f1 = fminf(fmaxf(f1, -127.f), 127.f);
    float f2 = rintf((t - f1) * 256.f);
    f2 = fminf(fmaxf(f2, -127.f), 127.f);
    l1 = (int)f1; l2 = (int)f2;
}
__device__ __forceinline__ unsigned pack4(int b0, int b1, int b2, int b3) {
    return (unsigned)(b0 & 0xFF) | ((unsigned)(b1 & 0xFF) << 8) |
           ((unsigned)(b2 & 0xFF) << 16) | ((unsigned)(b3 & 0xFF) << 24);
}

// ============================================================================
// Static device scratch (referenced ONLY from device code)
// ============================================================================
__device__ float       d_g[NROWS];
__device__ signed char d_a1[(size_t)NROWS * KA];     // [g*x | t] limb1
__device__ signed char d_a2[(size_t)NROWS * KA];     // limb2
__device__ signed char d_x1[(size_t)NROWS * IN_F];   // x limbs (for lr1 GEMM)
__device__ signed char d_x2[(size_t)NROWS * IN_F];
__device__ signed char d_w1[(size_t)OUT_F * IN_F];   // masked W limbs (scale 1024)
__device__ signed char d_w2[(size_t)OUT_F * IN_F];
__device__ signed char d_l1[(size_t)OUT_F * N_LR];   // lr2^T limbs (scale 256)
__device__ signed char d_l2[(size_t)OUT_F * N_LR];
__device__ signed char d_p1[(size_t)N_LR * IN_F];    // lr1^T limbs (scale 1024)
__device__ signed char d_p2[(size_t)N_LR * IN_F];
__device__ unsigned int  d_keys[NBLOCKS];
__device__ unsigned int  d_hist1[65536];
__device__ unsigned int  d_hist2[65536];
__device__ unsigned char d_active[NBLOCKS];
__device__ int           d_tied[65536];
__device__ int           d_tiedCnt;
__device__ unsigned int  d_selB;
__device__ unsigned int  d_selK1;
__device__ unsigned int  d_tau;
__device__ int           d_selR;

// ============================================================================
// Mask pipeline (unchanged from passing baseline)
// ============================================================================
__global__ void zeroK() {
    int i = blockIdx.x * blockDim.x + threadIdx.x;
    if (i < 65536)       d_hist1[i] = 0u;
    else if (i < 131072) d_hist2[i - 65536] = 0u;
    if (i == 0) d_tiedCnt = 0;
}

__global__ void gateK(const float* __restrict__ x, const float* __restrict__ gw,
                      const float* __restrict__ gb) {
    int warp = (blockIdx.x * blockDim.x + threadIdx.x) >> 5;
    int lane = threadIdx.x & 31;
    if (warp >= NROWS) return;
    const float4* xr = (const float4*)(x + (size_t)warp * IN_F);
    const float4* wv = (const float4*)gw;
    float s = 0.f;
    #pragma unroll 4
    for (int i = lane; i < IN_F / 4; i += 32) {
        float4 a = xr[i], b = wv[i];
        s += a.x * b.x + a.y * b.y + a.z * b.z + a.w * b.w;
    }
    #pragma unroll
    for (int o = 16; o; o >>= 1) s += __shfl_xor_sync(0xffffffffu, s, o);
    if (lane == 0) {
        float z = s + gb[0];
        d_g[warp] = 1.f / (1.f + expf(-z));
    }
}

__global__ void pooledK(const float* __restrict__ W) {
    int b = blockIdx.x * blockDim.x + threadIdx.x;
    if (b >= NBLOCKS) return;
    int bi = b / XB, bj = b % XB;
    int r0 = bi * 6, c0 = bj * 6;
    int rn = min(r0 + 6, IN_F), cn = min(c0 + 6, OUT_F);
    float s = 0.f;
    for (int r = r0; r < rn; ++r)
        for (int c = c0; c < cn; ++c)
            s += fabsf(W[(size_t)c * IN_F + r]);
    float p = s / (float)((rn - r0) * (cn - c0));
    unsigned int u = __float_as_uint(p);
    u = (u & 0x80000000u) ? ~u : (u | 0x80000000u);
    d_keys[b] = u;
    atomicAdd(&d_hist1[u >> 16], 1u);
}

__global__ void selectK(int pass) {
    __shared__ unsigned int csum[256];
    __shared__ unsigned int bins[256];
    __shared__ int sChunk;
    __shared__ unsigned int sG;
    const unsigned int* hist = (pass == 1) ? d_hist1 : d_hist2;
    unsigned int k = (pass == 1) ? (unsigned int)KSEL : d_selK1;
    int tid = threadIdx.x;
    unsigned int s = 0;
    for (int i = 0; i < 256; i++) s += hist[tid * 256 + i];
    csum[tid] = s;
    __syncthreads();
    if (tid == 0) {
        unsigned int c = 0; int ch = 255;
        for (; ch > 0; --ch) { if (c + csum[ch] >= k) break; c += csum[ch]; }
        sChunk = ch; sG = c;
    }
    __syncthreads();
    bins[tid] = hist[sChunk * 256 + tid];
    __syncthreads();
    if (tid == 0) {
        unsigned int c = sG; int bb = 255;
        for (; bb > 0; --bb) { if (c + bins[bb] >= k) break; c += bins[bb]; }
        unsigned int bin = (unsigned int)(sChunk * 256 + bb);
        if (pass == 1) { d_selB = bin; d_selK1 = k - c; }
        else           { d_tau = (d_selB << 16) | bin; d_selR = (int)(k - c); }
    }
}

__global__ void hist2K() {
    int b = blockIdx.x * blockDim.x + threadIdx.x;
    if (b >= NBLOCKS) return;
    unsigned int key = d_keys[b];
    if ((key >> 16) == d_selB) atomicAdd(&d_hist2[key & 0xFFFFu], 1u);
}

__global__ void markK() {
    int b = blockIdx.x * blockDim.x + threadIdx.x;
    if (b >= NBLOCKS) return;
    unsigned int key = d_keys[b];
    unsigned int tau = d_tau;
    d_active[b] = (key > tau) ? (unsigned char)1 : (unsigned char)0;
    if (key == tau) {
        int p = atomicAdd(&d_tiedCnt, 1);
        if (p < 65536) d_tied[p] = b;
    }
}

__global__ void resolveK() {
    if (threadIdx.x != 0 || blockIdx.x != 0) return;
    int T = d_tiedCnt; if (T > 65536) T = 65536;
    int r = d_selR;
    if (r >= T) { for (int i = 0; i < T; i++) d_active[d_tied[i]] = 1; return; }
    for (int i = 0; i < r; i++) {
        int best = i;
        for (int j = i + 1; j < T; j++)
            if (d_tied[j] < d_tied[best]) best = j;
        int tmp = d_tied[i]; d_tied[i] = d_tied[best]; d_tied[best] = tmp;
        d_active[d_tied[i]] = 1;
    }
}

// ============================================================================
// Quantization kernels
// ============================================================================
// x -> x limbs (scale 16) AND g*x limbs into A cols 0..4095 (scale 16)
__global__ void quantXK(const float* __restrict__ x) {
    int idx = blockIdx.x * blockDim.x + threadIdx.x;
    if (idx >= NROWS * (IN_F / 4)) return;
    int row = idx >> 10;
    int c4 = (idx & 1023) * 4;
    float g = d_g[row];
    float4 v = *(const float4*)(x + (size_t)row * IN_F + c4);
    int a, b, c2, d2, e, f, h, i2;
    q2(v.x, 16.f, a, b); q2(v.y, 16.f, c2, d2);
    q2(v.z, 16.f, e, f); q2(v.w, 16.f, h, i2);
    *(unsigned*)(d_x1 + (size_t)row * IN_F + c4) = pack4(a, c2, e, h);
    *(unsigned*)(d_x2 + (size_t)row * IN_F + c4) = pack4(b, d2, f, i2);
    q2(g * v.x, 16.f, a, b); q2(g * v.y, 16.f, c2, d2);
    q2(g * v.z, 16.f, e, f); q2(g * v.w, 16.f, h, i2);
    *(unsigned*)(d_a1 + (size_t)row * KA + c4) = pack4(a, c2, e, h);
    *(unsigned*)(d_a2 + (size_t)row * KA + c4) = pack4(b, d2, f, i2);
}

// masked W -> limbs (scale 1024)
__global__ void quantWK(const float* __restrict__ W) {
    int idx = blockIdx.x * blockDim.x + threadIdx.x;
    if (idx >= OUT_F * (IN_F / 4)) return;
    int n = idx >> 10;
    int k4 = (idx & 1023) * 4;
    float4 w = *(const float4*)(W + (size_t)n * IN_F + k4);
    int nb = n / 6;
    float v0 = d_active[((k4 + 0) / 6) * XB + nb] ? w.x : 0.f;
    float v1 = d_active[((k4 + 1) / 6) * XB + nb] ? w.y : 0.f;
    float v2 = d_active[((k4 + 2) / 6) * XB + nb] ? w.z : 0.f;
    float v3 = d_active[((k4 + 3) / 6) * XB + nb] ? w.w : 0.f;
    int a, b, c2, d2, e, f, h, i2;
    q2(v0, 1024.f, a, b); q2(v1, 1024.f, c2, d2);
    q2(v2, 1024.f, e, f); q2(v3, 1024.f, h, i2);
    *(unsigned*)(d_w1 + (size_t)n * IN_F + k4) = pack4(a, c2, e, h);
    *(unsigned*)(d_w2 + (size_t)n * IN_F + k4) = pack4(b, d2, f, i2);
}

// lr2^T -> limbs: rows n (OUT_F) x k (N_LR), val = (k<RANK)? lr2[k][n] : 0, scale 256
__global__ void quantL2K(const float* __restrict__ lr2) {
    int idx = blockIdx.x * blockDim.x + threadIdx.x;
    if (idx >= OUT_F * (N_LR / 4)) return;
    int n = idx / (N_LR / 4);
    int k4 = (idx - n * (N_LR / 4)) * 4;
    float v[4];
    #pragma unroll
    for (int i = 0; i < 4; i++)
        v[i] = (k4 + i < RANK) ? lr2[(size_t)(k4 + i) * OUT_F + n] : 0.f;
    int a, b, c2, d2, e, f, h, i2;
    q2(v[0], 256.f, a, b); q2(v[1], 256.f, c2, d2);
    q2(v[2], 256.f, e, f); q2(v[3], 256.f, h, i2);
    *(unsigned*)(d_l1 + (size_t)n * N_LR + k4) = pack4(a, c2, e, h);
    *(unsigned*)(d_l2 + (size_t)n * N_LR + k4) = pack4(b, d2, f, i2);
}

// lr1^T -> limbs: rows n (N_LR) x k (IN_F), val = (n<RANK)? lr1[k][n] : 0, scale 1024
__global__ void quantP1K(const float* __restrict__ lr1) {
    int idx = blockIdx.x * blockDim.x + threadIdx.x;
    if (idx >= N_LR * (IN_F / 4)) return;
    int n = idx >> 10;
    int k4 = (idx & 1023) * 4;
    float v[4];
    #pragma unroll
    for (int i = 0; i < 4; i++)
        v[i] = (n < RANK) ? lr1[(size_t)(k4 + i) * RANK + n] : 0.f;
    int a, b, c2, d2, e, f, h, i2;
    q2(v[0], 1024.f, a, b); q2(v[1], 1024.f, c2, d2);
    q2(v[2], 1024.f, e, f); q2(v[3], 1024.f, h, i2);
    *(unsigned*)(d_p1 + (size_t)n * IN_F + k4) = pack4(a, c2, e, h);
    *(unsigned*)(d_p2 + (size_t)n * IN_F + k4) = pack4(b, d2, f, i2);
}

// ============================================================================
// int8 2-limb GEMM (3 IMMA products per k32): C = A*B^T, s32-exact then scaled.
// MODE 0 (LR1):  A=x limbs, B=lr1^T limbs; epi: t=(1-g)*acc -> limbs into A cols 4096+
// MODE 1 (MAIN): A=g*x limbs, B=maskW limbs; epi: out = acc + g*bs + (1-g)*bl
// MODE 2 (ADD):  A=t limbs, B=lr2^T limbs;   epi: out += acc
// ============================================================================
template<int MODE>
__global__ __launch_bounds__(256, 1) void immaK(
    const float* __restrict__ bsp, const float* __restrict__ blp,
    float* __restrict__ out) {
    extern __shared__ __align__(1024) char smem[];
    unsigned sb = smem_u32(smem);
    int tid = threadIdx.x;

    const signed char* A1p = (MODE == 0) ? d_x1 : d_a1 + (MODE == 2 ? IN_F : 0);
    const signed char* A2p = (MODE == 0) ? d_x2 : d_a2 + (MODE == 2 ? IN_F : 0);
    const signed char* B1p = (MODE == 0) ? d_p1 : (MODE == 1 ? d_w1 : d_l1);
    const signed char* B2p = (MODE == 0) ? d_p2 : (MODE == 1 ? d_w2 : d_l2);
    const int lda = (MODE == 0) ? IN_F : KA;
    const int ldb = (MODE == 2) ? N_LR : IN_F;
    const int nch = (MODE == 2) ? (N_LR / BKC) : (IN_F / BKC);
    const int pn  = (MODE == 0) ? (N_LR / BN) : (OUT_F / BN);

    int pid = blockIdx.x;
    const int GM = 8;
    int grp = pid / (GM * pn);
    int mt  = grp * GM + (pid % GM);
    int nt  = (pid % (GM * pn)) / GM;
    int m0 = mt * BM, n0 = nt * BN;

    // stage loader (lambda-free inline): each thread covers one row-half (64B) per tile
    int lrow = tid >> 1, lh = tid & 1;
    const signed char* pa1 = A1p + (size_t)(m0 + lrow) * lda + lh * 64;
    const signed char* pa2 = A2p + (size_t)(m0 + lrow) * lda + lh * 64;
    const signed char* pb1 = B1p + (size_t)(n0 + lrow) * ldb + lh * 64;
    const signed char* pb2 = B2p + (size_t)(n0 + lrow) * ldb + lh * 64;
    unsigned drow = (unsigned)(lrow * 128);

    #pragma unroll
    for (int st = 0; st < 2; st++) {
        unsigned base = sb + st * STG;
        int k0 = st * BKC;
        #pragma unroll
        for (int j = 0; j < 4; j++) {
            unsigned d = drow + (unsigned)((((lh * 4 + j) ^ (lrow & 7)) * 16));
            cpasync16(base + 0 * TILE_B + d, pa1 + k0 + j * 16);
            cpasync16(base + 1 * TILE_B + d, pa2 + k0 + j * 16);
            cpasync16(base + 2 * TILE_B + d, pb1 + k0 + j * 16);
            cpasync16(base + 3 * TILE_B + d, pb2 + k0 + j * 16);
        }
        CP_COMMIT();
    }

    int wid = tid >> 5, lane = tid & 31;
    int wm = wid >> 2, wn = wid & 3;                         // 2 x 4 warps
    int ar = wm * 64 + (lane & 7) + ((lane >> 3) & 1) * 8;   // + mi*16
    int cA = lane >> 4;
    int br = wn * 32 + (lane & 7) + (lane >> 4) * 8;         // + g*16
    int cB = (lane >> 3) & 1;

    int acc2[4][4][4];   // A1*B1 level
    int acc3[4][4][4];   // A1*B2 + A2*B1 level
    #pragma unroll
    for (int a = 0; a < 4; a++)
        #pragma unroll
        for (int b = 0; b < 4; b++)
            #pragma unroll
            for (int c = 0; c < 4; c++) { acc2[a][b][c] = 0; acc3[a][b][c] = 0; }

    for (int ch = 0; ch < nch; ch++) {
        CP_WAIT1();
        __syncthreads();
        if (ch + 2 < nch) {
            unsigned base = sb + ((ch + 2) % NSTAGE) * STG;
            int k0 = (ch + 2) * BKC;
            #pragma unroll
            for (int j = 0; j < 4; j++) {
                unsigned d = drow + (unsigned)((((lh * 4 + j) ^ (lrow & 7)) * 16));
                cpasync16(base + 0 * TILE_B + d, pa1 + k0 + j * 16);
                cpasync16(base + 1 * TILE_B + d, pa2 + k0 + j * 16);
                cpasync16(base + 2 * TILE_B + d, pb1 + k0 + j * 16);
                cpasync16(base + 3 * TILE_B + d, pb2 + k0 + j * 16);
            }
        }
        CP_COMMIT();
        unsigned base = sb + (ch % NSTAGE) * STG;
        #pragma unroll
        for (int kk = 0; kk < 4; kk++) {
            uint4 fa1[4], fa2[4], fb1[2], fb2[2];
            #pragma unroll
            for (int mi = 0; mi < 4; mi++) {
                int r = ar + mi * 16;
                unsigned off = (unsigned)(r * 128 + (((kk * 2 + cA) ^ (r & 7)) * 16));
                fa1[mi] = ldsm4(base + off);
                fa2[mi] = ldsm4(base + TILE_B + off);
            }
            #pragma unroll
            for (int g = 0; g < 2; g++) {
                int r = br + g * 16;
                unsigned off = (unsigned)(r * 128 + (((kk * 2 + cB) ^ (r & 7)) * 16));
                fb1[g] = ldsm4(base + 2 * TILE_B + off);
                fb2[g] = ldsm4(base + 3 * TILE_B + off);
            }
            #pragma unroll
            for (int mi = 0; mi < 4; mi++)
                #pragma unroll
                for (int g = 0; g < 2; g++) {
                    imma(acc2[mi][2 * g],     fa1[mi], fb1[g].x, fb1[g].y);
                    imma(acc2[mi][2 * g + 1], fa1[mi], fb1[g].z, fb1[g].w);
                    imma(acc3[mi][2 * g],     fa1[mi], fb2[g].x, fb2[g].y);
                    imma(acc3[mi][2 * g + 1], fa1[mi], fb2[g].z, fb2[g].w);
                    imma(acc3[mi][2 * g],     fa2[mi], fb1[g].x, fb1[g].y);
                    imma(acc3[mi][2 * g + 1], fa2[mi], fb1[g].z, fb1[g].w);
                }
        }
    }

    // scale: MODE 0/1: (1/16)*(1/1024) = 2^-14; MODE 2: (1/16)*(1/256) = 2^-12
    const float SC = (MODE == 2) ? 2.44140625e-04f : 6.103515625e-05f;
    #pragma unroll
    for (int mi = 0; mi < 4; mi++) {
        #pragma unroll
        for (int r2 = 0; r2 < 2; r2++) {
            int m = m0 + wm * 64 + mi * 16 + (lane >> 2) + r2 * 8;
            float g = d_g[m];
            float og = 1.f - g;
            #pragma unroll
            for (int n8 = 0; n8 < 4; n8++) {
                int col = n0 + wn * 32 + n8 * 8 + (lane & 3) * 2;
                float v0 = ((float)acc2[mi][n8][r2 * 2] +
                            (float)acc3[mi][n8][r2 * 2] * 0.00390625f) * SC;
                float v1 = ((float)acc2[mi][n8][r2 * 2 + 1] +
                            (float)acc3[mi][n8][r2 * 2 + 1] * 0.00390625f) * SC;
                if (MODE == 1) {
                    float2 b1 = *(const float2*)(bsp + col);
                    float2 b2 = *(const float2*)(blp + col);
                    float2 o;
                    o.x = v0 + g * b1.x + og * b2.x;
                    o.y = v1 + g * b1.y + og * b2.y;
                    *(float2*)(out + (size_t)m * OUT_F + col) = o;
                } else if (MODE == 2) {
                    float2 o = *(float2*)(out + (size_t)m * OUT_F + col);
                    o.x += v0; o.y += v1;
                    *(float2*)(out + (size_t)m * OUT_F + col) = o;
                } else {
                    // t = (1-g)*v, quantize at scale 16 into A cols 4096+
                    int l1a, l2a, l1b, l2b;
                    q2(og * v0, 16.f, l1a, l2a);
                    q2(og * v1, 16.f, l1b, l2b);
                    size_t o = (size_t)m * KA + IN_F + col;
                    *(short*)(d_a1 + o) = (short)((l1a & 0xFF) | ((l1b & 0xFF) << 8));
                    *(short*)(d_a2 + o) = (short)((l2a & 0xFF) | ((l2b & 0xFF) << 8));
                }
            }
        }
    }
}

// ============================================================================
// launch
// ============================================================================
extern "C" void kernel_launch(void* const* d_in, const int* in_sizes, int n_in,
                              void* d_out, int out_size) {
    const float* x      = (const float*)d_in[0];
    const float* gate_w = (const float*)d_in[1];
    const float* gate_b = (const float*)d_in[2];
    const float* weight = (const float*)d_in[3];
    const float* s_bias = (const float*)d_in[4];
    const float* lr1    = (const float*)d_in[5];
    const float* lr2    = (const float*)d_in[6];
    const float* l_bias = (const float*)d_in[7];
    float* out = (float*)d_out;

    cudaFuncSetAttribute(immaK<0>, cudaFuncAttributeMaxDynamicSharedMemorySize, SMEM_GEMM);
    cudaFuncSetAttribute(immaK<1>, cudaFuncAttributeMaxDynamicSharedMemorySize, SMEM_GEMM);
    cudaFuncSetAttribute(immaK<2>, cudaFuncAttributeMaxDynamicSharedMemorySize, SMEM_GEMM);

    // order chosen so launch index 5 (ncu -s 5 -c 1) = immaK<0> (GEMM profile)
    gateK<<<(NROWS * 32 + 255) / 256, 256>>>(x, gate_w, gate_b);          // 0
    quantXK<<<(NROWS * (IN_F / 4) + 255) / 256, 256>>>(x);                // 1
    quantP1K<<<(N_LR * (IN_F / 4) + 255) / 256, 256>>>(lr1);              // 2
    zeroK<<<(131072 + 255) / 256, 256>>>();                               // 3
    pooledK<<<(NBLOCKS + 255) / 256, 256>>>(weight);                      // 4
    // lowrank1: t = (1-g)*(x @ lr1) -> limbs into A cols 4096..4607
    immaK<0><<<(NROWS / BM) * (N_LR / BN), 256, SMEM_GEMM>>>(             // 5
        nullptr, nullptr, nullptr);
    selectK<<<1, 256>>>(1);                                               // 6
    hist2K<<<(NBLOCKS + 255) / 256, 256>>>();                             // 7
    selectK<<<1, 256>>>(2);                                               // 8
    markK<<<(NBLOCKS + 255) / 256, 256>>>();                              // 9
    resolveK<<<1, 1>>>();                                                 // 10
    quantWK<<<(OUT_F * (IN_F / 4) + 255) / 256, 256>>>(weight);           // 11
    quantL2K<<<(OUT_F * (N_LR / 4) + 255) / 256, 256>>>(lr2);             // 12
    // main: out = g*x @ maskW^T + g*bs + (1-g)*bl
    immaK<1><<<(NROWS / BM) * (OUT_F / BN), 256, SMEM_GEMM>>>(            // 13
        s_bias, l_bias, out);
    // add: out += t @ lr2
    immaK<2><<<(NROWS / BM) * (OUT_F / BN), 256, SMEM_GEMM>>>(            // 14
        nullptr, nullptr, out);
}

// round 6
// speedup vs baseline: 2.8682x; 2.8682x over previous
#include <cuda_runtime.h>
#include <cuda_bf16.h>
#include <math.h>

#define IN_F   4096
#define OUT_F  4096
#define NROWS  16384
#define RANK   409
#define RANKP  448                 // pad so KCAT = 71*64
#define KCAT   (IN_F + RANKP)      // 4544
#define N_LR   512                 // lowrank N padded (4 tiles of 128)
#define XB     683
#define NBLOCKS (683*683)
#define KSEL   46649

#define BM 128
#define BN 128
#define BK 64
#define TILE_B 16384               // one operand tile: 128 rows x 128B
#define STG    (4*TILE_B)          // Ah,Al,Bh,Bl per stage
#define NSTAGE 3
#define SMEM_GEMM (NSTAGE*STG)     // 196608
#define NTHREADS 512

// ============================================================================
// helpers
// ============================================================================
__device__ __forceinline__ unsigned smem_u32(const void* p) {
    unsigned a;
    asm("{ .reg .u64 t; cvta.to.shared.u64 t, %1; cvt.u32.u64 %0, t; }" : "=r"(a) : "l"(p));
    return a;
}
__device__ __forceinline__ void cpasync16(unsigned dst, const void* src) {
    asm volatile("cp.async.cg.shared.global [%0], [%1], 16;" :: "r"(dst), "l"(src));
}
#define CP_COMMIT() asm volatile("cp.async.commit_group;" ::: "memory")
#define CP_WAIT1()  asm volatile("cp.async.wait_group 1;" ::: "memory")

__device__ __forceinline__ uint4 ldsm4(unsigned a) {
    uint4 r;
    asm volatile("ldmatrix.sync.aligned.m8n8.x4.shared.b16 {%0,%1,%2,%3}, [%4];"
                 : "=r"(r.x), "=r"(r.y), "=r"(r.z), "=r"(r.w) : "r"(a));
    return r;
}
__device__ __forceinline__ void mma16816(float* c, uint4 a, unsigned b0, unsigned b1) {
    asm volatile("mma.sync.aligned.m16n8k16.row.col.f32.bf16.bf16.f32 "
                 "{%0,%1,%2,%3},{%4,%5,%6,%7},{%8,%9},{%0,%1,%2,%3};"
                 : "+f"(c[0]), "+f"(c[1]), "+f"(c[2]), "+f"(c[3])
                 : "r"(a.x), "r"(a.y), "r"(a.z), "r"(a.w), "r"(b0), "r"(b1));
}
__device__ __forceinline__ void split2(float f0, float f1, unsigned& h, unsigned& l) {
    __nv_bfloat16 h0 = __float2bfloat16_rn(f0);
    __nv_bfloat16 h1 = __float2bfloat16_rn(f1);
    float r0 = f0 - __bfloat162float(h0);
    float r1 = f1 - __bfloat162float(h1);
    __nv_bfloat162 hh; hh.x = h0; hh.y = h1;
    __nv_bfloat162 ll; ll.x = __float2bfloat16_rn(r0); ll.y = __float2bfloat16_rn(r1);
    h = *reinterpret_cast<unsigned*>(&hh);
    l = *reinterpret_cast<unsigned*>(&ll);
}

// ============================================================================
// Static device scratch (referenced ONLY from device code)
// ============================================================================
__device__ float         d_g[NROWS];
__device__ __nv_bfloat16 d_ah[(size_t)NROWS * KCAT];   // [g*x | t] hi
__device__ __nv_bfloat16 d_al[(size_t)NROWS * KCAT];   // [g*x | t] lo
__device__ __nv_bfloat16 d_xh[(size_t)NROWS * IN_F];   // x hi (lowrank A)
__device__ __nv_bfloat16 d_xl[(size_t)NROWS * IN_F];
__device__ __nv_bfloat16 d_bh[(size_t)OUT_F * KCAT];   // [maskW | lr2^T] hi
__device__ __nv_bfloat16 d_bl[(size_t)OUT_F * KCAT];
__device__ __nv_bfloat16 d_b1h[(size_t)N_LR * IN_F];   // lr1^T hi
__device__ __nv_bfloat16 d_b1l[(size_t)N_LR * IN_F];
__device__ unsigned int  d_keys[NBLOCKS];
__device__ unsigned int  d_hist1[65536];
__device__ unsigned int  d_hist2[65536];
__device__ unsigned char d_active[NBLOCKS];
__device__ int           d_tied[65536];
__device__ int           d_tiedCnt;
__device__ unsigned int  d_selB;
__device__ unsigned int  d_selK1;
__device__ unsigned int  d_tau;
__device__ int           d_selR;

// ============================================================================
// Mask pipeline (unchanged from passing baseline)
// ============================================================================
__global__ void zeroK() {
    int i = blockIdx.x * blockDim.x + threadIdx.x;
    if (i < 65536)       d_hist1[i] = 0u;
    else if (i < 131072) d_hist2[i - 65536] = 0u;
    if (i == 0) d_tiedCnt = 0;
}

__global__ void gateK(const float* __restrict__ x, const float* __restrict__ gw,
                      const float* __restrict__ gb) {
    int warp = (blockIdx.x * blockDim.x + threadIdx.x) >> 5;
    int lane = threadIdx.x & 31;
    if (warp >= NROWS) return;
    const float4* xr = (const float4*)(x + (size_t)warp * IN_F);
    const float4* wv = (const float4*)gw;
    float s = 0.f;
    #pragma unroll 4
    for (int i = lane; i < IN_F / 4; i += 32) {
        float4 a = xr[i], b = wv[i];
        s += a.x * b.x + a.y * b.y + a.z * b.z + a.w * b.w;
    }
    #pragma unroll
    for (int o = 16; o; o >>= 1) s += __shfl_xor_sync(0xffffffffu, s, o);
    if (lane == 0) {
        float z = s + gb[0];
        d_g[warp] = 1.f / (1.f + expf(-z));
    }
}

__global__ void pooledK(const float* __restrict__ W) {
    int b = blockIdx.x * blockDim.x + threadIdx.x;
    if (b >= NBLOCKS) return;
    int bi = b / XB, bj = b % XB;
    int r0 = bi * 6, c0 = bj * 6;
    int rn = min(r0 + 6, IN_F), cn = min(c0 + 6, OUT_F);
    float s = 0.f;
    for (int r = r0; r < rn; ++r)
        for (int c = c0; c < cn; ++c)
            s += fabsf(W[(size_t)c * IN_F + r]);
    float p = s / (float)((rn - r0) * (cn - c0));
    unsigned int u = __float_as_uint(p);
    u = (u & 0x80000000u) ? ~u : (u | 0x80000000u);
    d_keys[b] = u;
    atomicAdd(&d_hist1[u >> 16], 1u);
}

__global__ void selectK(int pass) {
    __shared__ unsigned int csum[256];
    __shared__ unsigned int bins[256];
    __shared__ int sChunk;
    __shared__ unsigned int sG;
    const unsigned int* hist = (pass == 1) ? d_hist1 : d_hist2;
    unsigned int k = (pass == 1) ? (unsigned int)KSEL : d_selK1;
    int tid = threadIdx.x;
    unsigned int s = 0;
    for (int i = 0; i < 256; i++) s += hist[tid * 256 + i];
    csum[tid] = s;
    __syncthreads();
    if (tid == 0) {
        unsigned int c = 0; int ch = 255;
        for (; ch > 0; --ch) { if (c + csum[ch] >= k) break; c += csum[ch]; }
        sChunk = ch; sG = c;
    }
    __syncthreads();
    bins[tid] = hist[sChunk * 256 + tid];
    __syncthreads();
    if (tid == 0) {
        unsigned int c = sG; int bb = 255;
        for (; bb > 0; --bb) { if (c + bins[bb] >= k) break; c += bins[bb]; }
        unsigned int bin = (unsigned int)(sChunk * 256 + bb);
        if (pass == 1) { d_selB = bin; d_selK1 = k - c; }
        else           { d_tau = (d_selB << 16) | bin; d_selR = (int)(k - c); }
    }
}

__global__ void hist2K() {
    int b = blockIdx.x * blockDim.x + threadIdx.x;
    if (b >= NBLOCKS) return;
    unsigned int key = d_keys[b];
    if ((key >> 16) == d_selB) atomicAdd(&d_hist2[key & 0xFFFFu], 1u);
}

__global__ void markK() {
    int b = blockIdx.x * blockDim.x + threadIdx.x;
    if (b >= NBLOCKS) return;
    unsigned int key = d_keys[b];
    unsigned int tau = d_tau;
    d_active[b] = (key > tau) ? (unsigned char)1 : (unsigned char)0;
    if (key == tau) {
        int p = atomicAdd(&d_tiedCnt, 1);
        if (p < 65536) d_tied[p] = b;
    }
}

__global__ void resolveK() {
    if (threadIdx.x != 0 || blockIdx.x != 0) return;
    int T = d_tiedCnt; if (T > 65536) T = 65536;
    int r = d_selR;
    if (r >= T) { for (int i = 0; i < T; i++) d_active[d_tied[i]] = 1; return; }
    for (int i = 0; i < r; i++) {
        int best = i;
        for (int j = i + 1; j < T; j++)
            if (d_tied[j] < d_tied[best]) best = j;
        int tmp = d_tied[i]; d_tied[i] = d_tied[best]; d_tied[best] = tmp;
        d_active[d_tied[i]] = 1;
    }
}

// ============================================================================
// build B = [maskW | lr2^T] -> bf16 hi/lo     (rows n: OUT_F, cols k: KCAT)
// ============================================================================
__global__ void buildBK(const float* __restrict__ W, const float* __restrict__ lr2) {
    int idx = blockIdx.x * blockDim.x + threadIdx.x;
    if (idx >= OUT_F * (KCAT / 4)) return;
    int n = idx / (KCAT / 4);
    int q = (idx - n * (KCAT / 4)) * 4;
    float v[4];
    if (q < IN_F) {
        float4 w = *(const float4*)(W + (size_t)n * IN_F + q);
        int nb = n / 6;
        v[0] = d_active[((q + 0) / 6) * XB + nb] ? w.x : 0.f;
        v[1] = d_active[((q + 1) / 6) * XB + nb] ? w.y : 0.f;
        v[2] = d_active[((q + 2) / 6) * XB + nb] ? w.z : 0.f;
        v[3] = d_active[((q + 3) / 6) * XB + nb] ? w.w : 0.f;
    } else {
        int r = q - IN_F;
        #pragma unroll
        for (int i = 0; i < 4; i++)
            v[i] = (r + i < RANK) ? lr2[(size_t)(r + i) * OUT_F + n] : 0.f;
    }
    unsigned h0, l0, h1, l1;
    split2(v[0], v[1], h0, l0);
    split2(v[2], v[3], h1, l1);
    *(uint2*)((char*)d_bh + ((size_t)n * KCAT + q) * 2) = make_uint2(h0, h1);
    *(uint2*)((char*)d_bl + ((size_t)n * KCAT + q) * 2) = make_uint2(l0, l1);
}

// B1 = lr1^T padded to N_LR rows -> bf16 hi/lo
__global__ void buildB1K(const float* __restrict__ lr1) {
    int idx = blockIdx.x * blockDim.x + threadIdx.x;
    if (idx >= N_LR * (IN_F / 4)) return;
    int n = idx / (IN_F / 4);
    int q = (idx - n * (IN_F / 4)) * 4;
    float v[4];
    #pragma unroll
    for (int i = 0; i < 4; i++)
        v[i] = (n < RANK) ? lr1[(size_t)(q + i) * RANK + n] : 0.f;
    unsigned h0, l0, h1, l1;
    split2(v[0], v[1], h0, l0);
    split2(v[2], v[3], h1, l1);
    *(uint2*)((char*)d_b1h + ((size_t)n * IN_F + q) * 2) = make_uint2(h0, h1);
    *(uint2*)((char*)d_b1l + ((size_t)n * IN_F + q) * 2) = make_uint2(l0, l1);
}

// fused: x -> (xh, xl) AND g*x -> (ah, al) cols 0..IN_F-1 (single read of x)
__global__ void splitXK(const float* __restrict__ x) {
    int idx = blockIdx.x * blockDim.x + threadIdx.x;
    if (idx >= NROWS * (IN_F / 4)) return;
    int e = idx * 4;
    int row = e >> 12;
    int col = e & 4095;
    float g = d_g[row];
    float4 v = ((const float4*)x)[idx];
    unsigned h0, l0, h1, l1;
    split2(v.x, v.y, h0, l0);
    split2(v.z, v.w, h1, l1);
    ((uint2*)d_xh)[idx] = make_uint2(h0, h1);
    ((uint2*)d_xl)[idx] = make_uint2(l0, l1);
    split2(g * v.x, g * v.y, h0, l0);
    split2(g * v.z, g * v.w, h1, l1);
    size_t o = (size_t)row * KCAT + col;
    *(uint2*)((char*)d_ah + o * 2) = make_uint2(h0, h1);
    *(uint2*)((char*)d_al + o * 2) = make_uint2(l0, l1);
}

// ============================================================================
// bf16x3 GEMM via mma.sync.m16n8k16 + cp.async 3-stage pipeline.
// 512 threads, 16 warps (4x4), warp tile 32x32 -> 4 warps/SMSP latency hiding.
// MAIN: A=[g*x|t] (lda=KCAT), B=[maskW|lr2^T], out = acc + g*bs + (1-g)*bl
// LR:   A=x (lda=IN_F), B=lr1^T, epilogue writes t=(1-g)*acc into d_ah/d_al
// ============================================================================
__device__ __forceinline__ void load_stage(unsigned sbase,
    const __nv_bfloat16* __restrict__ Ah, const __nv_bfloat16* __restrict__ Al,
    int lda, int m0,
    const __nv_bfloat16* __restrict__ Bh, const __nv_bfloat16* __restrict__ Bl,
    int ldb, int n0, int k0, int tid) {
    int row = tid >> 2;                 // 0..127
    int q   = tid & 3;                  // quarter of the 128B row
    const __nv_bfloat16* a_h = Ah + (size_t)(m0 + row) * lda + k0 + q * 16;
    const __nv_bfloat16* a_l = Al + (size_t)(m0 + row) * lda + k0 + q * 16;
    const __nv_bfloat16* b_h = Bh + (size_t)(n0 + row) * ldb + k0 + q * 16;
    const __nv_bfloat16* b_l = Bl + (size_t)(n0 + row) * ldb + k0 + q * 16;
    unsigned drow = (unsigned)(row * 128);
    #pragma unroll
    for (int j = 0; j < 2; j++) {
        unsigned d = drow + (unsigned)((((q * 2 + j) ^ (row & 7)) * 16));
        cpasync16(sbase + 0 * TILE_B + d, a_h + j * 8);
        cpasync16(sbase + 1 * TILE_B + d, a_l + j * 8);
        cpasync16(sbase + 2 * TILE_B + d, b_h + j * 8);
        cpasync16(sbase + 3 * TILE_B + d, b_l + j * 8);
    }
}

template<bool MAIN>
__global__ __launch_bounds__(NTHREADS, 1) void mmaK(
    const float* __restrict__ bsp, const float* __restrict__ blp,
    float* __restrict__ out) {
    extern __shared__ __align__(1024) char smem[];
    unsigned sb = smem_u32(smem);
    int tid = threadIdx.x;

    // device-side operand selection (NEVER pass __device__ symbols from host!)
    const __nv_bfloat16* Ah = MAIN ? d_ah : d_xh;
    const __nv_bfloat16* Al = MAIN ? d_al : d_xl;
    const __nv_bfloat16* Bh = MAIN ? d_bh : d_b1h;
    const __nv_bfloat16* Bl = MAIN ? d_bl : d_b1l;
    const int lda = MAIN ? KCAT : IN_F;
    const int ldb = MAIN ? KCAT : IN_F;
    const int nch = MAIN ? (KCAT / BK) : (IN_F / BK);
    const int pn  = MAIN ? (OUT_F / BN) : (N_LR / BN);

    // CTA raster: groups of 8 m-tiles to keep B strips L2-resident
    int pid = blockIdx.x;
    const int GM = 8;
    int grp = pid / (GM * pn);
    int mt  = grp * GM + (pid % GM);
    int nt  = (pid % (GM * pn)) / GM;
    int m0 = mt * BM, n0 = nt * BN;

    // prologue: stages 0,1
    load_stage(sb + 0 * STG, Ah, Al, lda, m0, Bh, Bl, ldb, n0, 0, tid);
    CP_COMMIT();
    load_stage(sb + 1 * STG, Ah, Al, lda, m0, Bh, Bl, ldb, n0, BK, tid);
    CP_COMMIT();

    int wid = tid >> 5, lane = tid & 31;
    int wm = wid >> 2, wn = wid & 3;                         // 4 x 4 warps
    int ar = wm * 32 + (lane & 7) + ((lane >> 3) & 1) * 8;   // + mi*16
    int cA = lane >> 4;
    int br = wn * 32 + (lane & 7) + (lane >> 4) * 8;         // + g*16
    int cB = (lane >> 3) & 1;

    float acc[2][4][4];
    #pragma unroll
    for (int a = 0; a < 2; a++)
        #pragma unroll
        for (int b = 0; b < 4; b++)
            #pragma unroll
            for (int c = 0; c < 4; c++) acc[a][b][c] = 0.f;

    for (int ch = 0; ch < nch; ch++) {
        CP_WAIT1();
        __syncthreads();
        if (ch + 2 < nch)
            load_stage(sb + ((ch + 2) % NSTAGE) * STG, Ah, Al, lda, m0,
                       Bh, Bl, ldb, n0, (ch + 2) * BK, tid);
        CP_COMMIT();
        unsigned base = sb + (ch % NSTAGE) * STG;
        #pragma unroll
        for (int kk = 0; kk < 4; kk++) {
            uint4 fah[2], fal[2], fbh[2], fbl[2];
            #pragma unroll
            for (int mi = 0; mi < 2; mi++) {
                int r = ar + mi * 16;
                unsigned off = (unsigned)(r * 128 + (((kk * 2 + cA) ^ (r & 7)) * 16));
                fah[mi] = ldsm4(base + off);
                fal[mi] = ldsm4(base + TILE_B + off);
            }
            #pragma unroll
            for (int g = 0; g < 2; g++) {
                int r = br + g * 16;
                unsigned off = (unsigned)(r * 128 + (((kk * 2 + cB) ^ (r & 7)) * 16));
                fbh[g] = ldsm4(base + 2 * TILE_B + off);
                fbl[g] = ldsm4(base + 3 * TILE_B + off);
            }
            #pragma unroll
            for (int mi = 0; mi < 2; mi++)
                #pragma unroll
                for (int g = 0; g < 2; g++) {
                    mma16816(acc[mi][2 * g],     fah[mi], fbh[g].x, fbh[g].y);
                    mma16816(acc[mi][2 * g + 1], fah[mi], fbh[g].z, fbh[g].w);
                    mma16816(acc[mi][2 * g],     fah[mi], fbl[g].x, fbl[g].y);
                    mma16816(acc[mi][2 * g + 1], fah[mi], fbl[g].z, fbl[g].w);
                    mma16816(acc[mi][2 * g],     fal[mi], fbh[g].x, fbh[g].y);
                    mma16816(acc[mi][2 * g + 1], fal[mi], fbh[g].z, fbh[g].w);
                }
        }
    }

    // epilogue
    #pragma unroll
    for (int mi = 0; mi < 2; mi++) {
        #pragma unroll
        for (int r2 = 0; r2 < 2; r2++) {
            int m = m0 + wm * 32 + mi * 16 + (lane >> 2) + r2 * 8;
            float g = d_g[m];
            float og = 1.f - g;
            #pragma unroll
            for (int n8 = 0; n8 < 4; n8++) {
                int col = n0 + wn * 32 + n8 * 8 + (lane & 3) * 2;
                float a0 = acc[mi][n8][r2 * 2];
                float a1 = acc[mi][n8][r2 * 2 + 1];
                if (MAIN) {
                    float2 b1 = *(const float2*)(bsp + col);
                    float2 b2 = *(const float2*)(blp + col);
                    float2 o;
                    o.x = a0 + g * b1.x + og * b2.x;
                    o.y = a1 + g * b1.y + og * b2.y;
                    *(float2*)(out + (size_t)m * OUT_F + col) = o;
                } else {
                    if (col < RANKP) {
                        unsigned h, l;
                        split2(og * a0, og * a1, h, l);
                        size_t o = (size_t)m * KCAT + IN_F + col;
                        *(unsigned*)((char*)d_ah + o * 2) = h;
                        *(unsigned*)((char*)d_al + o * 2) = l;
                    }
                }
            }
        }
    }
}

// ============================================================================
// launch
// ============================================================================
extern "C" void kernel_launch(void* const* d_in, const int* in_sizes, int n_in,
                              void* d_out, int out_size) {
    const float* x      = (const float*)d_in[0];
    const float* gate_w = (const float*)d_in[1];
    const float* gate_b = (const float*)d_in[2];
    const float* weight = (const float*)d_in[3];
    const float* s_bias = (const float*)d_in[4];
    const float* lr1    = (const float*)d_in[5];
    const float* lr2    = (const float*)d_in[6];
    const float* l_bias = (const float*)d_in[7];
    float* out = (float*)d_out;

    cudaFuncSetAttribute(mmaK<false>, cudaFuncAttributeMaxDynamicSharedMemorySize, SMEM_GEMM);
    cudaFuncSetAttribute(mmaK<true>,  cudaFuncAttributeMaxDynamicSharedMemorySize, SMEM_GEMM);

    // launch index 3 = LR1 GEMM (ncu empirically captures index 3)
    gateK<<<(NROWS * 32 + 255) / 256, 256>>>(x, gate_w, gate_b);          // 0
    splitXK<<<(NROWS * (IN_F / 4) + 255) / 256, 256>>>(x);                // 1
    buildB1K<<<(N_LR * (IN_F / 4) + 255) / 256, 256>>>(lr1);              // 2
    mmaK<false><<<(NROWS / BM) * (N_LR / BN), NTHREADS, SMEM_GEMM>>>(     // 3
        nullptr, nullptr, nullptr);
    zeroK<<<(131072 + 255) / 256, 256>>>();                               // 4
    pooledK<<<(NBLOCKS + 255) / 256, 256>>>(weight);                      // 5
    selectK<<<1, 256>>>(1);                                               // 6
    hist2K<<<(NBLOCKS + 255) / 256, 256>>>();                             // 7
    selectK<<<1, 256>>>(2);                                               // 8
    markK<<<(NBLOCKS + 255) / 256, 256>>>();                              // 9
    resolveK<<<1, 1>>>();                                                 // 10
    buildBK<<<(OUT_F * (KCAT / 4) + 255) / 256, 256>>>(weight, lr2);      // 11
    // main: out = [g*x | t] @ [maskW | lr2^T]^T + g*bs + (1-g)*bl
    mmaK<true><<<(NROWS / BM) * (OUT_F / BN), NTHREADS, SMEM_GEMM>>>(     // 12
        s_bias, l_bias, out);
}